// round 16
// baseline (speedup 1.0000x reference)
#include <cuda_runtime.h>
#include <cuda_bf16.h>
#include <cstddef>
#include <cstdint>

#define NN   100000
#define NPAD 100096   // 1564 * 64
#define EE   1600000
#define BN_EPS 1e-5f

// ---------------- scratch (device globals; no allocation allowed) ----------------
__device__ __align__(16) float g_h  [(size_t)NPAD * 128];
__device__ __align__(16) float g_t1 [(size_t)NPAD * 256];
__device__ __align__(16) float g_hc [(size_t)NPAD * 128];
// pre-activation for GEMM0, stored pre-split as bf16 hi/lo (written by agg)
__device__ __align__(16) __nv_bfloat16 g_preh[(size_t)NPAD * 128];
__device__ __align__(16) __nv_bfloat16 g_prel[(size_t)NPAD * 128];
// BN stats, double-buffered per layer (slot = layer)
__device__ __align__(16) float g_sum1[2 * 256];
__device__ __align__(16) float g_sq1 [2 * 256];
__device__ __align__(16) float g_sum2[2 * 128];
__device__ __align__(16) float g_sq2 [2 * 128];
// BN affine (written by last GEMM block via counter)
__device__ __align__(16) float g_a1[256];
__device__ __align__(16) float g_c1[256];
__device__ __align__(16) float g_a2[128];
__device__ __align__(16) float g_c2[128];
__device__ int g_cnt[4];          // last-block counters: MODE*2 + layer
// pre-split weights (bf16 hi/lo), layer-major
__device__ __align__(16) __nv_bfloat16 g_W1h[2 * 32768];
__device__ __align__(16) __nv_bfloat16 g_W1l[2 * 32768];
__device__ __align__(16) __nv_bfloat16 g_W2h[2 * 32768];
__device__ __align__(16) __nv_bfloat16 g_W2l[2 * 32768];
// CSR build
__device__ int g_deg[NN];
__device__ int g_cur[NN];
__device__ int g_off[NN + 1];
__device__ int g_bsum[512];
__device__ int g_es[EE];          // packed: src | a0<<20 | a1<<23 | a2<<26

// ---------------- helpers ----------------
__device__ __forceinline__ uint32_t smem_u32(const void* p) {
    uint32_t a;
    asm("{ .reg .u64 t; cvta.to.shared.u64 t, %1; cvt.u32.u64 %0, t; }" : "=r"(a) : "l"(p));
    return a;
}

__device__ __forceinline__ void ldsm_x4(uint32_t (&r)[4], uint32_t addr) {
    asm volatile("ldmatrix.sync.aligned.m8n8.x4.shared.b16 {%0,%1,%2,%3}, [%4];"
                 : "=r"(r[0]), "=r"(r[1]), "=r"(r[2]), "=r"(r[3]) : "r"(addr));
}

__device__ __forceinline__ void ldsm_x2_t(uint32_t (&r)[2], uint32_t addr) {
    asm volatile("ldmatrix.sync.aligned.m8n8.x2.trans.shared.b16 {%0,%1}, [%2];"
                 : "=r"(r[0]), "=r"(r[1]) : "r"(addr));
}

__device__ __forceinline__ void mma16816(float (&d)[4], const uint32_t (&a)[4],
                                         const uint32_t (&b)[2]) {
    asm volatile("mma.sync.aligned.m16n8k16.row.col.f32.bf16.bf16.f32 "
                 "{%0,%1,%2,%3}, {%4,%5,%6,%7}, {%8,%9}, {%0,%1,%2,%3};"
                 : "+f"(d[0]), "+f"(d[1]), "+f"(d[2]), "+f"(d[3])
                 : "r"(a[0]), "r"(a[1]), "r"(a[2]), "r"(a[3]), "r"(b[0]), "r"(b[1]));
}

__device__ __forceinline__ uint32_t sw128(uint32_t off) {
    return off ^ ((off >> 3) & 0x70);
}

// split fp32 pair -> packed bf16x2 hi + bf16x2 lo
__device__ __forceinline__ void split2(float x, float y, uint32_t& hi, uint32_t& lo) {
    __nv_bfloat162 h = __floats2bfloat162_rn(x, y);
    float hx = __low2float(h), hy = __high2float(h);
    __nv_bfloat162 l = __floats2bfloat162_rn(x - hx, y - hy);
    hi = *reinterpret_cast<uint32_t*>(&h);
    lo = *reinterpret_cast<uint32_t*>(&l);
}

// BN affine from raw stats: a = gamma*rsqrt(var+eps), b = beta - mean*a
__device__ __forceinline__ void bn_affine(float s, float q, float gamma, float beta,
                                          float& a, float& b) {
    float mean = s * (1.f / NN);
    float var  = q * (1.f / NN) - mean * mean;
    float inv  = rsqrtf(var + BN_EPS);
    a = gamma * inv;
    b = beta - mean * a;
}

// ---------------- h0 = sum_f atom_emb[f][x[:,f]] + z_emb[z]  (+ zero deg/cur) -------
__global__ void embed_kernel(const int* __restrict__ x, const int* __restrict__ z,
                             const float* __restrict__ atom, const float* __restrict__ zemb) {
    int gid = blockIdx.x * blockDim.x + threadIdx.x;
    int node = gid >> 5;
    if (node >= NN) return;
    int lane = gid & 31;
    if (lane == 0) { g_deg[node] = 0; g_cur[node] = 0; }
    int c = lane * 4;
    const int* xr = x + node * 9;
    float4 acc = *(const float4*)&zemb[(size_t)z[node] * 128 + c];
#pragma unroll
    for (int f = 0; f < 9; f++) {
        int idx = xr[f];
        float4 v = *(const float4*)&atom[((size_t)(f * 119 + idx)) * 128 + c];
        acc.x += v.x; acc.y += v.y; acc.z += v.z; acc.w += v.w;
    }
    *(float4*)&g_h[(size_t)node * 128 + c] = acc;
}

// ---------------- pre-split weights into bf16 hi/lo (+ zero BN stats/counters) -----
__global__ void prep_w(const float* __restrict__ W1, const float* __restrict__ W2) {
    int i = blockIdx.x * blockDim.x + threadIdx.x;
    if (i >= 2 * 32768) return;
    if (i < 512) { g_sum1[i] = 0.f; g_sq1[i] = 0.f; }
    if (i < 256) { g_sum2[i] = 0.f; g_sq2[i] = 0.f; }
    if (i < 4)   g_cnt[i] = 0;
    float w = W1[i];
    __nv_bfloat16 h = __float2bfloat16_rn(w);
    g_W1h[i] = h; g_W1l[i] = __float2bfloat16_rn(w - __bfloat162float(h));
    w = W2[i];
    h = __float2bfloat16_rn(w);
    g_W2h[i] = h; g_W2l[i] = __float2bfloat16_rn(w - __bfloat162float(h));
}

// ---------------- CSR build (once per launch; edge_index is layer-invariant) ------
__global__ void hist_kernel(const int* __restrict__ ei) {
    int e = blockIdx.x * blockDim.x + threadIdx.x;
    if (e < EE) atomicAdd(&g_deg[ei[EE + e]], 1);
}

__global__ void scan1_kernel() {
    __shared__ int s[256];
    int i = blockIdx.x * 256 + threadIdx.x;
    s[threadIdx.x] = (i < NN) ? g_deg[i] : 0;
    __syncthreads();
    for (int o = 128; o > 0; o >>= 1) {
        if (threadIdx.x < o) s[threadIdx.x] += s[threadIdx.x + o];
        __syncthreads();
    }
    if (threadIdx.x == 0) g_bsum[blockIdx.x] = s[0];
}

__global__ void scan2_kernel(int nb) {
    if (threadIdx.x == 0 && blockIdx.x == 0) {
        int s = 0;
        for (int i = 0; i < nb; i++) { int t = g_bsum[i]; g_bsum[i] = s; s += t; }
        g_off[NN] = s;
    }
}

__global__ void scan3_kernel() {
    __shared__ int s[256];
    int i = blockIdx.x * 256 + threadIdx.x;
    int v = (i < NN) ? g_deg[i] : 0;
    s[threadIdx.x] = v;
    __syncthreads();
    for (int o = 1; o < 256; o <<= 1) {
        int t = (threadIdx.x >= o) ? s[threadIdx.x - o] : 0;
        __syncthreads();
        s[threadIdx.x] += t;
        __syncthreads();
    }
    if (i < NN) g_off[i] = g_bsum[blockIdx.x] + s[threadIdx.x] - v;
}

__global__ void scatter_kernel(const int* __restrict__ ei, const int* __restrict__ ea) {
    int e = blockIdx.x * blockDim.x + threadIdx.x;
    if (e >= EE) return;
    int dst = ei[EE + e];
    int pos = g_off[dst] + atomicAdd(&g_cur[dst], 1);
    int src = ei[e];
    int a0 = ea[e * 3 + 0] & 7, a1 = ea[e * 3 + 1] & 7, a2 = ea[e * 3 + 2] & 7;
    g_es[pos] = src | (a0 << 20) | (a1 << 23) | (a2 << 26);
}

// ---------------- aggregate (gather) --------------------------------------------
// BNF=0: h = g_h[.]                           (layer 0)
// BNF=1: h = relu(g_hc[.]*g_a2 + g_c2)        (affine precomputed by gemm1's last block)
// pre[d] = (1+eps)*h[d] + sum_edges relu(h[src] + bond), written SPLIT (bf16 hi/lo)
template <int BNF>
__global__ void agg_kernel(const float* __restrict__ bt, const float* __restrict__ epsp) {
    __shared__ float s_bond[18 * 128];   // 9KB: 3 tables x 6 rows x 128
    for (int i = threadIdx.x; i < 18 * 128; i += 256) s_bond[i] = bt[i];
    __syncthreads();

    int w = (blockIdx.x * 256 + threadIdx.x) >> 5;
    int lane = threadIdx.x & 31;
    int c = lane * 4;
    int beg = g_off[w], end = g_off[w + 1];
    float epsv = 1.f + epsp[0];

    float4 av, cv;
    if constexpr (BNF == 1) {
        av = *(const float4*)&g_a2[c];
        cv = *(const float4*)&g_c2[c];
    }

    auto LDH = [&](int src) -> float4 {
        if constexpr (BNF == 0) {
            return *(const float4*)&g_h[(size_t)src * 128 + c];
        } else {
            float4 v = *(const float4*)&g_hc[(size_t)src * 128 + c];
            float4 o;
            o.x = fmaxf(fmaf(v.x, av.x, cv.x), 0.f);
            o.y = fmaxf(fmaf(v.y, av.y, cv.y), 0.f);
            o.z = fmaxf(fmaf(v.z, av.z, cv.z), 0.f);
            o.w = fmaxf(fmaf(v.w, av.w, cv.w), 0.f);
            return o;
        }
    };

    float4 hv = LDH(w);
    float4 acc = make_float4(epsv * hv.x, epsv * hv.y, epsv * hv.z, epsv * hv.w);

    auto ACCUM = [&](const float4& h4, int pk) {
        const float4 b0 = *(const float4*)&s_bond[(((pk >> 20) & 7)) * 128 + c];
        const float4 b1 = *(const float4*)&s_bond[(6 + ((pk >> 23) & 7)) * 128 + c];
        const float4 b2 = *(const float4*)&s_bond[(12 + ((pk >> 26) & 7)) * 128 + c];
        acc.x += fmaxf(h4.x + b0.x + b1.x + b2.x, 0.f);
        acc.y += fmaxf(h4.y + b0.y + b1.y + b2.y, 0.f);
        acc.z += fmaxf(h4.z + b0.z + b1.z + b2.z, 0.f);
        acc.w += fmaxf(h4.w + b0.w + b1.w + b2.w, 0.f);
    };

    int p = beg;
    for (; p + 4 <= end; p += 4) {
        int pk0 = g_es[p + 0], pk1 = g_es[p + 1];
        int pk2 = g_es[p + 2], pk3 = g_es[p + 3];
        float4 h0 = LDH(pk0 & 0xFFFFF);
        float4 h1 = LDH(pk1 & 0xFFFFF);
        float4 h2 = LDH(pk2 & 0xFFFFF);
        float4 h3 = LDH(pk3 & 0xFFFFF);
        ACCUM(h0, pk0); ACCUM(h1, pk1); ACCUM(h2, pk2); ACCUM(h3, pk3);
    }
    for (; p < end; p++) {
        int pk = g_es[p];
        float4 h4 = LDH(pk & 0xFFFFF);
        ACCUM(h4, pk);
    }
    uint32_t h01, l01, h23, l23;
    split2(acc.x, acc.y, h01, l01);
    split2(acc.z, acc.w, h23, l23);
    *(uint2*)&g_preh[(size_t)w * 128 + c] = make_uint2(h01, h23);
    *(uint2*)&g_prel[(size_t)w * 128 + c] = make_uint2(l01, l23);
}

// ---------------- mma.sync bf16-split GEMM, 64x128 tile, 2 CTAs/SM ----------------
// R8/R10 double-buffer structure, register prefetch, LDG+STS staging.
// B from pre-split bf16 hi/lo globals; MODE0 A also pre-split (agg writes it).
// MODE 0: A = pre (bf16 hi/lo) [N,128];  C = A@W1 + b1 -> g_t1 [N,256] (grid.y=2)
// MODE 1: A = relu(g_t1*g_a1+g_c1) [N,256]; C = A@W2 + b2 -> g_hc [N,128] (grid.y=1)
// Epilogue: bias, store, fused BN column sums/sumsq (rows < NN) into slot `layer`;
// the LAST block (global counter) computes the BN affine into g_a*/g_c*.

#define STAGE_BYTES 49152                     // A hi 8K + A lo 8K + B hi 16K + B lo 16K
#define GEMM_SMEM   (2 * STAGE_BYTES + 2048)

template <int MODE>
__global__ __launch_bounds__(256, 2) void gemm_mma(const float* __restrict__ bias,
                                                   const float* __restrict__ gamma,
                                                   const float* __restrict__ beta,
                                                   int layer) {
    constexpr int KTOT   = (MODE == 0) ? 128 : 256;
    constexpr int NCHUNK = KTOT / 64;
    constexpr int NCOL   = (MODE == 0) ? 256 : 128;

    extern __shared__ char smem[];
    uint32_t sbase = smem_u32(smem);
    float* s_a1 = (float*)(smem + 2 * STAGE_BYTES);
    float* s_c1 = (float*)(smem + 2 * STAGE_BYTES + 1024);

    const __nv_bfloat16* Wh = (MODE == 0) ? (g_W1h + layer * 32768) : (g_W2h + layer * 32768);
    const __nv_bfloat16* Wl = (MODE == 0) ? (g_W1l + layer * 32768) : (g_W2l + layer * 32768);

    int t = threadIdx.x;
    int lane = t & 31;
    int wid = t >> 5;
    int wm = wid & 1;
    int wn = wid >> 1;
    int blockRow = blockIdx.x * 64;
    int c0 = blockIdx.y * 128;

    if constexpr (MODE == 1) {
        s_a1[t] = g_a1[t];           // precomputed by gemm0's last block
        s_c1[t] = g_c1[t];
        __syncthreads();
    }

    // staging maps (256 threads; A: 64x64, B: 64x128 per chunk)
    int arow = t >> 2;
    int ac0  = (t & 3) * 16;
    int bkr  = t >> 2;
    int bn0  = (t & 3) * 32;

    // mma lane addressing
    int a_r  = wm * 32 + (lane & 15);
    int a_kh = (lane >> 4) * 8;
    uint32_t swa = (uint32_t)((a_r & 7) << 4);
    int bl   = lane & 15;
    int b_k7 = bl & 7;
    int b_kh = ((bl >> 3) & 1) * 8;
    uint32_t nboff[4];
#pragma unroll
    for (int ni = 0; ni < 4; ni++)
        nboff[ni] = ((uint32_t)((wn * 32 + ni * 8) * 2)) ^ ((uint32_t)(b_k7 << 4));

    float acc[2][4][4];
#pragma unroll
    for (int mi = 0; mi < 2; mi++)
#pragma unroll
        for (int ni = 0; ni < 4; ni++)
#pragma unroll
            for (int j = 0; j < 4; j++) acc[mi][ni][j] = 0.f;

    // prefetch registers
    float4 hA[4];                 // MODE1 fp32
    uint2  pAh[4], pAl[4];        // MODE0 pre-split

    auto LOADA = [&](int kc) {
        size_t r = (size_t)(blockRow + arow);
        int kg = kc * 64 + ac0;
        if constexpr (MODE == 0) {
#pragma unroll
            for (int q = 0; q < 4; q++) {
                pAh[q] = *(const uint2*)&g_preh[r * 128 + kg + q * 4];
                pAl[q] = *(const uint2*)&g_prel[r * 128 + kg + q * 4];
            }
        } else {
#pragma unroll
            for (int q = 0; q < 4; q++)
                hA[q] = *(const float4*)&g_t1[r * 256 + kg + q * 4];
        }
    };
    auto STORE = [&](int s, int kc) {
        char* Ah = smem + s * STAGE_BYTES;
        char* Al = Ah + 8192;
        char* Bh = Ah + 16384;
        char* Bl = Ah + 32768;
#pragma unroll
        for (int q = 0; q < 4; q++) {
            int cl = ac0 + q * 4;
            uint32_t off = sw128((uint32_t)(arow * 128 + cl * 2));
            if constexpr (MODE == 0) {
                *(uint2*)(Ah + off) = pAh[q];
                *(uint2*)(Al + off) = pAl[q];
            } else {
                float4 a = hA[q];
                int kg = kc * 64 + cl;
                float4 sc = *(const float4*)&s_a1[kg];
                float4 sh = *(const float4*)&s_c1[kg];
                a.x = fmaxf(fmaf(a.x, sc.x, sh.x), 0.f);
                a.y = fmaxf(fmaf(a.y, sc.y, sh.y), 0.f);
                a.z = fmaxf(fmaf(a.z, sc.z, sh.z), 0.f);
                a.w = fmaxf(fmaf(a.w, sc.w, sh.w), 0.f);
                uint32_t h01, l01, h23, l23;
                split2(a.x, a.y, h01, l01);
                split2(a.z, a.w, h23, l23);
                *(uint2*)(Ah + off) = make_uint2(h01, h23);
                *(uint2*)(Al + off) = make_uint2(l01, l23);
            }
        }
        // B: plain copies from pre-split bf16 hi/lo (8B each)
        size_t wrow = (size_t)(kc * 64 + bkr) * NCOL + c0;
#pragma unroll
        for (int q = 0; q < 8; q++) {
            int n = bn0 + q * 4;
            uint2 hv = *(const uint2*)&Wh[wrow + n];
            uint2 lv = *(const uint2*)&Wl[wrow + n];
            uint32_t off = (uint32_t)(bkr * 256) +
                           (((uint32_t)(n * 2)) ^ ((uint32_t)((bkr & 7) << 4)));
            *(uint2*)(Bh + off) = hv;
            *(uint2*)(Bl + off) = lv;
        }
    };
    auto MMA = [&](int s) {
        uint32_t Au   = sbase + s * STAGE_BYTES;
        uint32_t Alou = Au + 8192;
        uint32_t Bu   = Au + 16384;
        uint32_t Blou = Au + 32768;
#pragma unroll
        for (int term = 0; term < 3; term++) {
            uint32_t Ab = (term == 2) ? Alou : Au;
            uint32_t Bb = (term == 1) ? Blou : Bu;
#pragma unroll
            for (int kk = 0; kk < 4; kk++) {
                int k0 = kk * 16;
                uint32_t a[2][4];
                uint32_t b[4][2];
                uint32_t kA = (((uint32_t)((k0 + a_kh) * 2)) ^ swa);
#pragma unroll
                for (int mi = 0; mi < 2; mi++)
                    ldsm_x4(a[mi], Ab + (uint32_t)((a_r + mi * 16) * 128) + kA);
                uint32_t kB = (uint32_t)((k0 + b_kh + b_k7) * 256);
#pragma unroll
                for (int ni = 0; ni < 4; ni++)
                    ldsm_x2_t(b[ni], Bb + kB + nboff[ni]);
#pragma unroll
                for (int mi = 0; mi < 2; mi++)
#pragma unroll
                    for (int ni = 0; ni < 4; ni++)
                        mma16816(acc[mi][ni], a[mi], b[ni]);
            }
        }
    };

    // ---- R8 double-buffer pipeline ----
    LOADA(0);
    STORE(0, 0);
    __syncthreads();
#pragma unroll
    for (int kc = 0; kc < NCHUNK; kc++) {
        if (kc + 1 < NCHUNK) LOADA(kc + 1);
        MMA(kc & 1);
        if (kc + 1 < NCHUNK) STORE((kc + 1) & 1, kc + 1);
        __syncthreads();
    }

    // ---- epilogue: bias add, store C, fused column stats (slot = layer) ----
    float* s_s = (float*)smem;
    float* s_q = (float*)smem + 128;
    if (t < 128) { s_s[t] = 0.f; s_q[t] = 0.f; }
    __syncthreads();

    float* Cout = (MODE == 0) ? g_t1 : g_hc;
    int gidl = lane >> 2, tq = lane & 3;
    int colbase = wn * 32 + tq * 2;
    float2 bv[4];
#pragma unroll
    for (int ni = 0; ni < 4; ni++)
        bv[ni] = *(const float2*)&bias[c0 + colbase + ni * 8];

    float ssum[4][2] = {}, qsum[4][2] = {};
#pragma unroll
    for (int mi = 0; mi < 2; mi++) {
        int r0 = blockRow + wm * 32 + mi * 16 + gidl;
        int r1 = r0 + 8;
        bool ok0 = r0 < NN, ok1 = r1 < NN;
#pragma unroll
        for (int ni = 0; ni < 4; ni++) {
            float v0 = acc[mi][ni][0] + bv[ni].x;
            float v1 = acc[mi][ni][1] + bv[ni].y;
            float v2 = acc[mi][ni][2] + bv[ni].x;
            float v3 = acc[mi][ni][3] + bv[ni].y;
            int col = c0 + colbase + ni * 8;
            if (ok0) {
                *(float2*)&Cout[(size_t)r0 * NCOL + col] = make_float2(v0, v1);
                ssum[ni][0] += v0; qsum[ni][0] += v0 * v0;
                ssum[ni][1] += v1; qsum[ni][1] += v1 * v1;
            }
            if (ok1) {
                *(float2*)&Cout[(size_t)r1 * NCOL + col] = make_float2(v2, v3);
                ssum[ni][0] += v2; qsum[ni][0] += v2 * v2;
                ssum[ni][1] += v3; qsum[ni][1] += v3 * v3;
            }
        }
    }
#pragma unroll
    for (int ni = 0; ni < 4; ni++) {
        int cl = colbase + ni * 8;
        atomicAdd(&s_s[cl], ssum[ni][0]);
        atomicAdd(&s_s[cl + 1], ssum[ni][1]);
        atomicAdd(&s_q[cl], qsum[ni][0]);
        atomicAdd(&s_q[cl + 1], qsum[ni][1]);
    }
    __syncthreads();
    float* Sg = (MODE == 0) ? (g_sum1 + layer * 256) : (g_sum2 + layer * 128);
    float* Qg = (MODE == 0) ? (g_sq1 + layer * 256)  : (g_sq2 + layer * 128);
    if (t < 128) {
        atomicAdd(&Sg[c0 + t], s_s[t]);
        atomicAdd(&Qg[c0 + t], s_q[t]);
    }

    // ---- last block computes BN affine (folded finalize) ----
    __shared__ int s_last;
    __threadfence();
    __syncthreads();
    if (t == 0) {
        int total = gridDim.x * gridDim.y;
        s_last = (atomicAdd(&g_cnt[MODE * 2 + layer], 1) == total - 1);
    }
    __syncthreads();
    if (s_last) {
        constexpr int C = (MODE == 0) ? 256 : 128;
        if (t < C) {
            float a, b;
            bn_affine(Sg[t], Qg[t], gamma[t], beta[t], a, b);
            if constexpr (MODE == 0) { g_a1[t] = a; g_c1[t] = b; }
            else                     { g_a2[t] = a; g_c2[t] = b; }
        }
    }
}

// ---------------- apply final BN (no relu), write d_out; affine precomputed --------
__global__ void bnapply_kernel(float* __restrict__ dst) {
    int gid = blockIdx.x * blockDim.x + threadIdx.x;
    int node = gid >> 5;
    if (node >= NN) return;
    int c = (gid & 31) * 4;
    float4 v = *(const float4*)&g_hc[(size_t)node * 128 + c];
    float4 a = *(const float4*)&g_a2[c];
    float4 b = *(const float4*)&g_c2[c];
    float4 o;
    o.x = v.x * a.x + b.x; o.y = v.y * a.y + b.y;
    o.z = v.z * a.z + b.z; o.w = v.w * a.w + b.w;
    *(float4*)&dst[(size_t)node * 128 + c] = o;
}

// ---------------- launch ----------------
extern "C" void kernel_launch(void* const* d_in, const int* in_sizes, int n_in,
                              void* d_out, int out_size) {
    const int*   x    = (const int*)d_in[0];
    const int*   z    = (const int*)d_in[1];
    const int*   ei   = (const int*)d_in[2];
    const int*   ea   = (const int*)d_in[3];
    const float* atom = (const float*)d_in[4];
    const float* zemb = (const float*)d_in[5];
    const float* bond = (const float*)d_in[6];
    const float* eps  = (const float*)d_in[7];
    const float* W1   = (const float*)d_in[8];
    const float* b1   = (const float*)d_in[9];
    const float* g1   = (const float*)d_in[10];
    const float* be1  = (const float*)d_in[11];
    const float* W2   = (const float*)d_in[12];
    const float* b2   = (const float*)d_in[13];
    const float* bng  = (const float*)d_in[14];
    const float* bnb  = (const float*)d_in[15];
    float* out = (float*)d_out;

    static bool attr_done = false;
    if (!attr_done) {
        cudaFuncSetAttribute(gemm_mma<0>, cudaFuncAttributeMaxDynamicSharedMemorySize, GEMM_SMEM);
        cudaFuncSetAttribute(gemm_mma<1>, cudaFuncAttributeMaxDynamicSharedMemorySize, GEMM_SMEM);
        attr_done = true;
    }

    const int NODE_BLKS = (NN * 32 + 255) / 256;   // 12500
    const int EDGE_BLKS = (EE + 255) / 256;        // 6250
    const int NB        = (NN + 255) / 256;        // 391

    embed_kernel<<<NODE_BLKS, 256>>>(x, z, atom, zemb);
    prep_w<<<256, 256>>>(W1, W2);

    hist_kernel<<<EDGE_BLKS, 256>>>(ei);
    scan1_kernel<<<NB, 256>>>();
    scan2_kernel<<<1, 32>>>(NB);
    scan3_kernel<<<NB, 256>>>();
    scatter_kernel<<<EDGE_BLKS, 256>>>(ei, ea);

    for (int l = 0; l < 2; l++) {
        if (l == 0)
            agg_kernel<0><<<NODE_BLKS, 256>>>(bond, eps);
        else
            agg_kernel<1><<<NODE_BLKS, 256>>>(bond + (size_t)3 * 6 * 128, eps + 1);
        gemm_mma<0><<<dim3(NPAD / 64, 2), 256, GEMM_SMEM>>>(b1 + l * 256,
                                                            g1 + l * 256, be1 + l * 256, l);
        gemm_mma<1><<<dim3(NPAD / 64, 1), 256, GEMM_SMEM>>>(b2 + l * 128,
                                                            bng + l * 128, bnb + l * 128, l);
    }
    bnapply_kernel<<<NODE_BLKS, 256>>>(out);
}

// round 17
// speedup vs baseline: 1.0507x; 1.0507x over previous
#include <cuda_runtime.h>
#include <cuda_bf16.h>
#include <cstddef>
#include <cstdint>

#define NN   100000
#define NPAD 100096   // 1564 * 64
#define EE   1600000

// ---------------- scratch (device globals; no allocation allowed) ----------------
__device__ __align__(16) float g_h  [(size_t)NPAD * 128];
__device__ __align__(16) float g_pre[(size_t)NPAD * 128];   // (1+eps)h + agg
__device__ __align__(16) float g_t1 [(size_t)NPAD * 256];
__device__ __align__(16) float g_hc [(size_t)NPAD * 128];
__device__ __align__(16) float g_sum1[256];
__device__ __align__(16) float g_sq1 [256];
__device__ __align__(16) float g_sum2[128];
__device__ __align__(16) float g_sq2 [128];
__device__ __align__(16) float g_a1[256];
__device__ __align__(16) float g_c1[256];
__device__ __align__(16) float g_a2[128];
__device__ __align__(16) float g_c2[128];
// pre-split weights (bf16 hi/lo), layer-major
__device__ __align__(16) __nv_bfloat16 g_W1h[2 * 32768];
__device__ __align__(16) __nv_bfloat16 g_W1l[2 * 32768];
__device__ __align__(16) __nv_bfloat16 g_W2h[2 * 32768];
__device__ __align__(16) __nv_bfloat16 g_W2l[2 * 32768];
// CSR build
__device__ int g_deg[NN];
__device__ int g_cur[NN];
__device__ int g_off[NN + 1];
__device__ int g_bsum[512];
__device__ int g_es[EE];          // packed: src | a0<<20 | a1<<23 | a2<<26

// ---------------- helpers ----------------
__device__ __forceinline__ uint32_t smem_u32(const void* p) {
    uint32_t a;
    asm("{ .reg .u64 t; cvta.to.shared.u64 t, %1; cvt.u32.u64 %0, t; }" : "=r"(a) : "l"(p));
    return a;
}

__device__ __forceinline__ void ldsm_x4(uint32_t (&r)[4], uint32_t addr) {
    asm volatile("ldmatrix.sync.aligned.m8n8.x4.shared.b16 {%0,%1,%2,%3}, [%4];"
                 : "=r"(r[0]), "=r"(r[1]), "=r"(r[2]), "=r"(r[3]) : "r"(addr));
}

__device__ __forceinline__ void ldsm_x2_t(uint32_t (&r)[2], uint32_t addr) {
    asm volatile("ldmatrix.sync.aligned.m8n8.x2.trans.shared.b16 {%0,%1}, [%2];"
                 : "=r"(r[0]), "=r"(r[1]) : "r"(addr));
}

__device__ __forceinline__ void mma16816(float (&d)[4], const uint32_t (&a)[4],
                                         const uint32_t (&b)[2]) {
    asm volatile("mma.sync.aligned.m16n8k16.row.col.f32.bf16.bf16.f32 "
                 "{%0,%1,%2,%3}, {%4,%5,%6,%7}, {%8,%9}, {%0,%1,%2,%3};"
                 : "+f"(d[0]), "+f"(d[1]), "+f"(d[2]), "+f"(d[3])
                 : "r"(a[0]), "r"(a[1]), "r"(a[2]), "r"(a[3]), "r"(b[0]), "r"(b[1]));
}

__device__ __forceinline__ uint32_t sw128(uint32_t off) {
    return off ^ ((off >> 3) & 0x70);
}

// split fp32 pair -> packed bf16x2 hi + bf16x2 lo
__device__ __forceinline__ void split2(float x, float y, uint32_t& hi, uint32_t& lo) {
    __nv_bfloat162 h = __floats2bfloat162_rn(x, y);
    float hx = __low2float(h), hy = __high2float(h);
    __nv_bfloat162 l = __floats2bfloat162_rn(x - hx, y - hy);
    hi = *reinterpret_cast<uint32_t*>(&h);
    lo = *reinterpret_cast<uint32_t*>(&l);
}

// ---------------- zero deg/cur (must precede fused front kernel) ----------------
__global__ void zero_kernel() {
    int i = blockIdx.x * blockDim.x + threadIdx.x;
    if (i < NN) { g_deg[i] = 0; g_cur[i] = 0; }
}

// ---------------- fused front: embed + hist + W-split (independent block ranges) ---
// blocks [0, 12500):        h0 = sum_f atom_emb[f][x[:,f]] + z_emb[z]
// blocks [12500, 18750):    hist: g_deg[dst]++
// blocks [18750, 19006):    split W1/W2 into bf16 hi/lo
#define EMBED_BLKS 12500
#define HIST_BLKS  6250
#define PREP_BLKS  256
__global__ void front_kernel(const int* __restrict__ x, const int* __restrict__ z,
                             const float* __restrict__ atom, const float* __restrict__ zemb,
                             const int* __restrict__ ei,
                             const float* __restrict__ W1, const float* __restrict__ W2) {
    int b = blockIdx.x;
    if (b < EMBED_BLKS) {
        int gid = b * 256 + threadIdx.x;
        int node = gid >> 5;
        if (node >= NN) return;
        int c = (gid & 31) * 4;
        const int* xr = x + node * 9;
        float4 acc = *(const float4*)&zemb[(size_t)z[node] * 128 + c];
#pragma unroll
        for (int f = 0; f < 9; f++) {
            int idx = xr[f];
            float4 v = *(const float4*)&atom[((size_t)(f * 119 + idx)) * 128 + c];
            acc.x += v.x; acc.y += v.y; acc.z += v.z; acc.w += v.w;
        }
        *(float4*)&g_h[(size_t)node * 128 + c] = acc;
    } else if (b < EMBED_BLKS + HIST_BLKS) {
        int e = (b - EMBED_BLKS) * 256 + threadIdx.x;
        if (e < EE) atomicAdd(&g_deg[ei[EE + e]], 1);
    } else {
        int i = (b - EMBED_BLKS - HIST_BLKS) * 256 + threadIdx.x;
        if (i >= 2 * 32768) return;
        float w = W1[i];
        __nv_bfloat16 h = __float2bfloat16_rn(w);
        g_W1h[i] = h; g_W1l[i] = __float2bfloat16_rn(w - __bfloat162float(h));
        w = W2[i];
        h = __float2bfloat16_rn(w);
        g_W2h[i] = h; g_W2l[i] = __float2bfloat16_rn(w - __bfloat162float(h));
    }
}

// ---------------- CSR scans ----------------
__global__ void scan1_kernel() {   // per-block sums of g_deg
    __shared__ int s[256];
    int i = blockIdx.x * 256 + threadIdx.x;
    s[threadIdx.x] = (i < NN) ? g_deg[i] : 0;
    __syncthreads();
    for (int o = 128; o > 0; o >>= 1) {
        if (threadIdx.x < o) s[threadIdx.x] += s[threadIdx.x + o];
        __syncthreads();
    }
    if (threadIdx.x == 0) g_bsum[blockIdx.x] = s[0];
}

__global__ void scan2_kernel(int nb) {   // PARALLEL exclusive scan of block sums
    __shared__ int s[512];
    int t = threadIdx.x;
    int v = (t < nb) ? g_bsum[t] : 0;
    s[t] = v;
    __syncthreads();
    for (int o = 1; o < 512; o <<= 1) {
        int u = (t >= o) ? s[t - o] : 0;
        __syncthreads();
        s[t] += u;
        __syncthreads();
    }
    if (t < nb) g_bsum[t] = s[t] - v;          // exclusive
    if (t == nb - 1) g_off[NN] = s[t];
}

__global__ void scan3_kernel() {   // per-block exclusive scan -> g_off
    __shared__ int s[256];
    int i = blockIdx.x * 256 + threadIdx.x;
    int v = (i < NN) ? g_deg[i] : 0;
    s[threadIdx.x] = v;
    __syncthreads();
    for (int o = 1; o < 256; o <<= 1) {
        int t = (threadIdx.x >= o) ? s[threadIdx.x - o] : 0;
        __syncthreads();
        s[threadIdx.x] += t;
        __syncthreads();
    }
    if (i < NN) g_off[i] = g_bsum[blockIdx.x] + s[threadIdx.x] - v;
}

__global__ void scatter_kernel(const int* __restrict__ ei, const int* __restrict__ ea) {
    int e = blockIdx.x * blockDim.x + threadIdx.x;
    if (e >= EE) return;
    int dst = ei[EE + e];
    int pos = g_off[dst] + atomicAdd(&g_cur[dst], 1);
    int src = ei[e];
    int a0 = ea[e * 3 + 0] & 7, a1 = ea[e * 3 + 1] & 7, a2 = ea[e * 3 + 2] & 7;
    g_es[pos] = src | (a0 << 20) | (a1 << 23) | (a2 << 26);
}

// ---------------- aggregate (gather) --------------------------------------------
// BNF=0: h = g_h[.]                       (layer 0)
// BNF=1: h = relu(g_hc[.]*a2 + c2)        (layer 1; folds previous bnapply)
// pre[d] = (1+eps)*h[d] + sum_edges relu(h[src] + bond)
// Block 0 additionally zeroes the BN stat accumulators for this layer.
template <int BNF>
__global__ void agg_kernel(const float* __restrict__ bt, const float* __restrict__ epsp) {
    __shared__ float s_bond[18 * 128];   // 9KB: 3 tables x 6 rows x 128
    for (int i = threadIdx.x; i < 18 * 128; i += 256) s_bond[i] = bt[i];
    if (blockIdx.x == 0) {
        int t = threadIdx.x;
        if (t < 256) { g_sum1[t] = 0.f; g_sq1[t] = 0.f; }
        if (t < 128) { g_sum2[t] = 0.f; g_sq2[t] = 0.f; }
    }
    __syncthreads();

    int w = (blockIdx.x * 256 + threadIdx.x) >> 5;
    int lane = threadIdx.x & 31;
    int c = lane * 4;
    int beg = g_off[w], end = g_off[w + 1];
    float epsv = 1.f + epsp[0];

    float4 av, cv;
    if constexpr (BNF == 1) {
        av = *(const float4*)&g_a2[c];
        cv = *(const float4*)&g_c2[c];
    }

    auto LDH = [&](int src) -> float4 {
        if constexpr (BNF == 0) {
            return *(const float4*)&g_h[(size_t)src * 128 + c];
        } else {
            float4 v = *(const float4*)&g_hc[(size_t)src * 128 + c];
            float4 o;
            o.x = fmaxf(fmaf(v.x, av.x, cv.x), 0.f);
            o.y = fmaxf(fmaf(v.y, av.y, cv.y), 0.f);
            o.z = fmaxf(fmaf(v.z, av.z, cv.z), 0.f);
            o.w = fmaxf(fmaf(v.w, av.w, cv.w), 0.f);
            return o;
        }
    };

    float4 hv = LDH(w);
    float4 acc = make_float4(epsv * hv.x, epsv * hv.y, epsv * hv.z, epsv * hv.w);

    auto ACCUM = [&](const float4& h4, int pk) {
        const float4 b0 = *(const float4*)&s_bond[(((pk >> 20) & 7)) * 128 + c];
        const float4 b1 = *(const float4*)&s_bond[(6 + ((pk >> 23) & 7)) * 128 + c];
        const float4 b2 = *(const float4*)&s_bond[(12 + ((pk >> 26) & 7)) * 128 + c];
        acc.x += fmaxf(h4.x + b0.x + b1.x + b2.x, 0.f);
        acc.y += fmaxf(h4.y + b0.y + b1.y + b2.y, 0.f);
        acc.z += fmaxf(h4.z + b0.z + b1.z + b2.z, 0.f);
        acc.w += fmaxf(h4.w + b0.w + b1.w + b2.w, 0.f);
    };

    int p = beg;
    for (; p + 4 <= end; p += 4) {
        int pk0 = g_es[p + 0], pk1 = g_es[p + 1];
        int pk2 = g_es[p + 2], pk3 = g_es[p + 3];
        float4 h0 = LDH(pk0 & 0xFFFFF);
        float4 h1 = LDH(pk1 & 0xFFFFF);
        float4 h2 = LDH(pk2 & 0xFFFFF);
        float4 h3 = LDH(pk3 & 0xFFFFF);
        ACCUM(h0, pk0); ACCUM(h1, pk1); ACCUM(h2, pk2); ACCUM(h3, pk3);
    }
    for (; p < end; p++) {
        int pk = g_es[p];
        float4 h4 = LDH(pk & 0xFFFFF);
        ACCUM(h4, pk);
    }
    *(float4*)&g_pre[(size_t)w * 128 + c] = acc;
}

// ---------------- mma.sync bf16-split GEMM, 64x128 tile, 2 CTAs/SM ----------------
// R8 champion structure: double-buffered 48KB stages, register prefetch, LDG+STS.
// B from pre-split bf16 hi/lo globals.
// MODE 0: A = g_pre [N,128];            C = A@W1 + b1 -> g_t1 [N,256] (grid.y=2)
// MODE 1: A = relu(g_t1*a1+c1) [N,256]; C = A@W2 + b2 -> g_hc [N,128] (grid.y=1)
// Epilogue: bias, store, fused BN column sums/sumsq (rows < NN).

#define STAGE_BYTES 49152                     // A hi 8K + A lo 8K + B hi 16K + B lo 16K
#define GEMM_SMEM   (2 * STAGE_BYTES + 2048)

template <int MODE>
__global__ __launch_bounds__(256, 2) void gemm_mma(const float* __restrict__ bias,
                                                   int layer) {
    constexpr int KTOT   = (MODE == 0) ? 128 : 256;
    constexpr int NCHUNK = KTOT / 64;
    constexpr int NCOL   = (MODE == 0) ? 256 : 128;

    extern __shared__ char smem[];
    uint32_t sbase = smem_u32(smem);
    float* s_a1 = (float*)(smem + 2 * STAGE_BYTES);
    float* s_c1 = (float*)(smem + 2 * STAGE_BYTES + 1024);

    const __nv_bfloat16* Wh = (MODE == 0) ? (g_W1h + layer * 32768) : (g_W2h + layer * 32768);
    const __nv_bfloat16* Wl = (MODE == 0) ? (g_W1l + layer * 32768) : (g_W2l + layer * 32768);

    int t = threadIdx.x;
    int lane = t & 31;
    int wid = t >> 5;
    int wm = wid & 1;        // 0..1 -> 32-row block
    int wn = wid >> 1;       // 0..3 -> 32-col block
    int blockRow = blockIdx.x * 64;
    int c0 = blockIdx.y * 128;

    if constexpr (MODE == 1) {
        if (t < 256) { s_a1[t] = g_a1[t]; s_c1[t] = g_c1[t]; }
        __syncthreads();
    }

    // staging maps (256 threads; A: 64x64, B: 64x128 per chunk)
    int arow = t >> 2;             // 0..63
    int ac0  = (t & 3) * 16;       // 0,16,32,48
    int bkr  = t >> 2;             // 0..63
    int bn0  = (t & 3) * 32;       // 0,32,64,96

    // mma lane addressing
    int a_r  = wm * 32 + (lane & 15);
    int a_kh = (lane >> 4) * 8;
    uint32_t swa = (uint32_t)((a_r & 7) << 4);
    int bl   = lane & 15;
    int b_k7 = bl & 7;
    int b_kh = ((bl >> 3) & 1) * 8;
    uint32_t nboff[4];
#pragma unroll
    for (int ni = 0; ni < 4; ni++)
        nboff[ni] = ((uint32_t)((wn * 32 + ni * 8) * 2)) ^ ((uint32_t)(b_k7 << 4));

    float acc[2][4][4];
#pragma unroll
    for (int mi = 0; mi < 2; mi++)
#pragma unroll
        for (int ni = 0; ni < 4; ni++)
#pragma unroll
            for (int j = 0; j < 4; j++) acc[mi][ni][j] = 0.f;

    float4 hA[4];   // A prefetch

    auto LOADA = [&](int kc) {
        size_t r = (size_t)(blockRow + arow);
        int kg = kc * 64 + ac0;
#pragma unroll
        for (int q = 0; q < 4; q++) {
            if constexpr (MODE == 0)
                hA[q] = *(const float4*)&g_pre[r * 128 + kg + q * 4];
            else
                hA[q] = *(const float4*)&g_t1[r * 256 + kg + q * 4];
        }
    };
    auto STORE = [&](int s, int kc) {
        char* Ah = smem + s * STAGE_BYTES;
        char* Al = Ah + 8192;
        char* Bh = Ah + 16384;
        char* Bl = Ah + 32768;
#pragma unroll
        for (int q = 0; q < 4; q++) {
            int cl = ac0 + q * 4;
            float4 a = hA[q];
            if constexpr (MODE == 1) {
                int kg = kc * 64 + cl;
                float4 sc = *(const float4*)&s_a1[kg];
                float4 sh = *(const float4*)&s_c1[kg];
                a.x = fmaxf(fmaf(a.x, sc.x, sh.x), 0.f);
                a.y = fmaxf(fmaf(a.y, sc.y, sh.y), 0.f);
                a.z = fmaxf(fmaf(a.z, sc.z, sh.z), 0.f);
                a.w = fmaxf(fmaf(a.w, sc.w, sh.w), 0.f);
            }
            uint32_t h01, l01, h23, l23;
            split2(a.x, a.y, h01, l01);
            split2(a.z, a.w, h23, l23);
            uint32_t off = sw128((uint32_t)(arow * 128 + cl * 2));
            *(uint2*)(Ah + off) = make_uint2(h01, h23);
            *(uint2*)(Al + off) = make_uint2(l01, l23);
        }
        // B: plain copies from pre-split bf16 hi/lo (8B each)
        size_t wrow = (size_t)(kc * 64 + bkr) * NCOL + c0;
#pragma unroll
        for (int q = 0; q < 8; q++) {
            int n = bn0 + q * 4;
            uint2 hv = *(const uint2*)&Wh[wrow + n];
            uint2 lv = *(const uint2*)&Wl[wrow + n];
            uint32_t off = (uint32_t)(bkr * 256) +
                           (((uint32_t)(n * 2)) ^ ((uint32_t)((bkr & 7) << 4)));
            *(uint2*)(Bh + off) = hv;
            *(uint2*)(Bl + off) = lv;
        }
    };
    auto MMA = [&](int s) {
        uint32_t Au   = sbase + s * STAGE_BYTES;
        uint32_t Alou = Au + 8192;
        uint32_t Bu   = Au + 16384;
        uint32_t Blou = Au + 32768;
#pragma unroll
        for (int term = 0; term < 3; term++) {
            uint32_t Ab = (term == 2) ? Alou : Au;
            uint32_t Bb = (term == 1) ? Blou : Bu;
#pragma unroll
            for (int kk = 0; kk < 4; kk++) {
                int k0 = kk * 16;
                uint32_t a[2][4];
                uint32_t b[4][2];
                uint32_t kA = (((uint32_t)((k0 + a_kh) * 2)) ^ swa);
#pragma unroll
                for (int mi = 0; mi < 2; mi++)
                    ldsm_x4(a[mi], Ab + (uint32_t)((a_r + mi * 16) * 128) + kA);
                uint32_t kB = (uint32_t)((k0 + b_kh + b_k7) * 256);
#pragma unroll
                for (int ni = 0; ni < 4; ni++)
                    ldsm_x2_t(b[ni], Bb + kB + nboff[ni]);
#pragma unroll
                for (int mi = 0; mi < 2; mi++)
#pragma unroll
                    for (int ni = 0; ni < 4; ni++)
                        mma16816(acc[mi][ni], a[mi], b[ni]);
            }
        }
    };

    // ---- R8 double-buffer pipeline ----
    LOADA(0);
    STORE(0, 0);
    __syncthreads();
#pragma unroll
    for (int kc = 0; kc < NCHUNK; kc++) {
        if (kc + 1 < NCHUNK) LOADA(kc + 1);
        MMA(kc & 1);
        if (kc + 1 < NCHUNK) STORE((kc + 1) & 1, kc + 1);
        __syncthreads();
    }

    // ---- epilogue: bias add, store C, fused column stats ----
    float* s_s = (float*)smem;
    float* s_q = (float*)smem + 128;
    if (t < 128) { s_s[t] = 0.f; s_q[t] = 0.f; }
    __syncthreads();

    float* Cout = (MODE == 0) ? g_t1 : g_hc;
    int gidl = lane >> 2, tq = lane & 3;
    int colbase = wn * 32 + tq * 2;
    float2 bv[4];
#pragma unroll
    for (int ni = 0; ni < 4; ni++)
        bv[ni] = *(const float2*)&bias[c0 + colbase + ni * 8];

    float ssum[4][2] = {}, qsum[4][2] = {};
#pragma unroll
    for (int mi = 0; mi < 2; mi++) {
        int r0 = blockRow + wm * 32 + mi * 16 + gidl;
        int r1 = r0 + 8;
        bool ok0 = r0 < NN, ok1 = r1 < NN;
#pragma unroll
        for (int ni = 0; ni < 4; ni++) {
            float v0 = acc[mi][ni][0] + bv[ni].x;
            float v1 = acc[mi][ni][1] + bv[ni].y;
            float v2 = acc[mi][ni][2] + bv[ni].x;
            float v3 = acc[mi][ni][3] + bv[ni].y;
            int col = c0 + colbase + ni * 8;
            if (ok0) {
                *(float2*)&Cout[(size_t)r0 * NCOL + col] = make_float2(v0, v1);
                ssum[ni][0] += v0; qsum[ni][0] += v0 * v0;
                ssum[ni][1] += v1; qsum[ni][1] += v1 * v1;
            }
            if (ok1) {
                *(float2*)&Cout[(size_t)r1 * NCOL + col] = make_float2(v2, v3);
                ssum[ni][0] += v2; qsum[ni][0] += v2 * v2;
                ssum[ni][1] += v3; qsum[ni][1] += v3 * v3;
            }
        }
    }
#pragma unroll
    for (int ni = 0; ni < 4; ni++) {
        int cl = colbase + ni * 8;
        atomicAdd(&s_s[cl], ssum[ni][0]);
        atomicAdd(&s_s[cl + 1], ssum[ni][1]);
        atomicAdd(&s_q[cl], qsum[ni][0]);
        atomicAdd(&s_q[cl + 1], qsum[ni][1]);
    }
    __syncthreads();
    if (t < 128) {
        float* Sg = (MODE == 0) ? g_sum1 : g_sum2;
        float* Qg = (MODE == 0) ? g_sq1 : g_sq2;
        atomicAdd(&Sg[c0 + t], s_s[t]);
        atomicAdd(&Qg[c0 + t], s_q[t]);
    }
}

// ---------------- finalize BN affine: a = g/sqrt(var+eps), b = beta - mean*a --------
template <int WHICH>
__global__ void finalize_kernel(const float* __restrict__ gamma,
                                const float* __restrict__ beta) {
    constexpr int C = (WHICH == 0) ? 256 : 128;
    int c = threadIdx.x;
    if (c >= C) return;
    float s = (WHICH == 0) ? g_sum1[c] : g_sum2[c];
    float q = (WHICH == 0) ? g_sq1[c]  : g_sq2[c];
    float mean = s * (1.f / NN);
    float var  = q * (1.f / NN) - mean * mean;
    float inv  = rsqrtf(var + 1e-5f);
    float a = gamma[c] * inv;
    float b = beta[c] - mean * a;
    if (WHICH == 0) { g_a1[c] = a; g_c1[c] = b; }
    else            { g_a2[c] = a; g_c2[c] = b; }
}

// ---------------- apply final BN (no relu), write d_out -----------
__global__ void bnapply_kernel(float* __restrict__ dst) {
    int gid = blockIdx.x * blockDim.x + threadIdx.x;
    int node = gid >> 5;
    if (node >= NN) return;
    int c = (gid & 31) * 4;
    float4 v = *(const float4*)&g_hc[(size_t)node * 128 + c];
    float4 a = *(const float4*)&g_a2[c];
    float4 b = *(const float4*)&g_c2[c];
    float4 o;
    o.x = v.x * a.x + b.x; o.y = v.y * a.y + b.y;
    o.z = v.z * a.z + b.z; o.w = v.w * a.w + b.w;
    *(float4*)&dst[(size_t)node * 128 + c] = o;
}

// ---------------- launch ----------------
extern "C" void kernel_launch(void* const* d_in, const int* in_sizes, int n_in,
                              void* d_out, int out_size) {
    const int*   x    = (const int*)d_in[0];
    const int*   z    = (const int*)d_in[1];
    const int*   ei   = (const int*)d_in[2];
    const int*   ea   = (const int*)d_in[3];
    const float* atom = (const float*)d_in[4];
    const float* zemb = (const float*)d_in[5];
    const float* bond = (const float*)d_in[6];
    const float* eps  = (const float*)d_in[7];
    const float* W1   = (const float*)d_in[8];
    const float* b1   = (const float*)d_in[9];
    const float* g1   = (const float*)d_in[10];
    const float* be1  = (const float*)d_in[11];
    const float* W2   = (const float*)d_in[12];
    const float* b2   = (const float*)d_in[13];
    const float* bng  = (const float*)d_in[14];
    const float* bnb  = (const float*)d_in[15];
    float* out = (float*)d_out;

    static bool attr_done = false;
    if (!attr_done) {
        cudaFuncSetAttribute(gemm_mma<0>, cudaFuncAttributeMaxDynamicSharedMemorySize, GEMM_SMEM);
        cudaFuncSetAttribute(gemm_mma<1>, cudaFuncAttributeMaxDynamicSharedMemorySize, GEMM_SMEM);
        attr_done = true;
    }

    const int NODE_BLKS = (NN * 32 + 255) / 256;   // 12500
    const int EDGE_BLKS = (EE + 255) / 256;        // 6250
    const int NB        = (NN + 255) / 256;        // 391

    zero_kernel<<<NB, 256>>>();
    front_kernel<<<EMBED_BLKS + HIST_BLKS + PREP_BLKS, 256>>>(x, z, atom, zemb, ei, W1, W2);
    scan1_kernel<<<NB, 256>>>();
    scan2_kernel<<<1, 512>>>(NB);
    scan3_kernel<<<NB, 256>>>();
    scatter_kernel<<<EDGE_BLKS, 256>>>(ei, ea);

    for (int l = 0; l < 2; l++) {
        if (l == 0)
            agg_kernel<0><<<NODE_BLKS, 256>>>(bond, eps);
        else
            agg_kernel<1><<<NODE_BLKS, 256>>>(bond + (size_t)3 * 6 * 128, eps + 1);
        gemm_mma<0><<<dim3(NPAD / 64, 2), 256, GEMM_SMEM>>>(b1 + l * 256, l);
        finalize_kernel<0><<<1, 256>>>(g1 + l * 256, be1 + l * 256);
        gemm_mma<1><<<dim3(NPAD / 64, 1), 256, GEMM_SMEM>>>(b2 + l * 128, l);
        finalize_kernel<1><<<1, 128>>>(bng + l * 128, bnb + l * 128);
    }
    bnapply_kernel<<<NODE_BLKS, 256>>>(out);
}